// round 12
// baseline (speedup 1.0000x reference)
#include <cuda_runtime.h>
#include <cuda_bf16.h>
#include <cuda_pipeline.h>
#include <mma.h>
#include <math.h>

using namespace nvcuda;
typedef unsigned long long ull;
typedef __nv_bfloat16 bf16;

#define B_  2
#define L_  2048
#define DM  1024
#define H_  16
#define DK  64
#define M_  (B_*L_)

#define X_ELEMS   ((size_t)M_*DM)
#define ATT_ELEMS ((size_t)B_*H_*L_*L_)

__device__ float g_O[M_*DM];
__device__ bf16 g_xh[3][M_*DM];
__device__ bf16 g_xl[3][M_*DM];
__device__ bf16 g_wh[4][DM*DM];
__device__ bf16 g_wl[4][DM*DM];
__device__ bf16 g_ch[M_*DM];
__device__ bf16 g_cl[M_*DM];
__device__ bf16 g_qh[M_*DM];
__device__ bf16 g_ql[M_*DM];
__device__ bf16 g_kh[M_*DM];
__device__ bf16 g_kl[M_*DM];
__device__ bf16 g_vb[M_*DM];

// ---------------- fp32 -> bf16 hi/lo split ----------------------------------
__global__ __launch_bounds__(256) void cvt_hilo(
    const float* __restrict__ src, bf16* __restrict__ hi,
    bf16* __restrict__ lo, int n4)
{
    int i = blockIdx.x * 256 + threadIdx.x;
    if (i >= n4) return;
    float4 v = ((const float4*)src)[i];
    bf16 h0 = __float2bfloat16_rn(v.x);
    bf16 h1 = __float2bfloat16_rn(v.y);
    bf16 h2 = __float2bfloat16_rn(v.z);
    bf16 h3 = __float2bfloat16_rn(v.w);
    __nv_bfloat162 ph0; ph0.x = h0; ph0.y = h1;
    __nv_bfloat162 ph1; ph1.x = h2; ph1.y = h3;
    __nv_bfloat162 pl0;
    pl0.x = __float2bfloat16_rn(v.x - __bfloat162float(h0));
    pl0.y = __float2bfloat16_rn(v.y - __bfloat162float(h1));
    __nv_bfloat162 pl1;
    pl1.x = __float2bfloat16_rn(v.z - __bfloat162float(h2));
    pl1.y = __float2bfloat16_rn(v.w - __bfloat162float(h3));
    ((__nv_bfloat162*)hi)[i*2+0] = ph0;
    ((__nv_bfloat162*)hi)[i*2+1] = ph1;
    ((__nv_bfloat162*)lo)[i*2+0] = pl0;
    ((__nv_bfloat162*)lo)[i*2+1] = pl1;
}

// ---------------- pipelined wmma GEMM core: C = A @ B^T ---------------------
// 3-term bf16 hi/lo, fp32 accum, BK=32, cp.async 3-stage ring.
#define ASTR 40
#define NSTG 3
#define TILE_E (128*ASTR)
#define STG_E  (4*TILE_E)
#define GEMM_SMEM (NSTG*STG_E*2)

__device__ __forceinline__ void gemm_core(
    const bf16* __restrict__ Ah, const bf16* __restrict__ Al,
    const bf16* __restrict__ Bh, const bf16* __restrict__ Bl,
    float* Cf, bf16* Chi, bf16* Clo, bf16* Cb,
    int Nd, int Kd, int m0, int n0, bf16* sg)
{
    int tid = threadIdx.x;
    int wid = tid >> 5;
    int wm = wid >> 1, wn = wid & 1;

    wmma::fragment<wmma::accumulator,16,16,16,float> acc[2][4];
    #pragma unroll
    for (int i=0;i<2;i++)
      #pragma unroll
      for (int j=0;j<4;j++) wmma::fill_fragment(acc[i][j], 0.0f);

    int row = tid >> 1, seg = (tid & 1) * 16;
    const bf16* s0 = Ah + (size_t)(m0+row)*Kd + seg;
    const bf16* s1 = Al + (size_t)(m0+row)*Kd + seg;
    const bf16* s2 = Bh + (size_t)(n0+row)*Kd + seg;
    const bf16* s3 = Bl + (size_t)(n0+row)*Kd + seg;
    bf16* dbase = sg + row*ASTR + seg;

    int NCH = Kd >> 5;
    #pragma unroll
    for (int s = 0; s < NSTG-1; s++) {
        bf16* d = dbase + s*STG_E;
        int kc = s*32;
        __pipeline_memcpy_async(d,            s0 + kc,     16);
        __pipeline_memcpy_async(d+8,          s0 + kc + 8, 16);
        __pipeline_memcpy_async(d+TILE_E,     s1 + kc,     16);
        __pipeline_memcpy_async(d+TILE_E+8,   s1 + kc + 8, 16);
        __pipeline_memcpy_async(d+2*TILE_E,   s2 + kc,     16);
        __pipeline_memcpy_async(d+2*TILE_E+8, s2 + kc + 8, 16);
        __pipeline_memcpy_async(d+3*TILE_E,   s3 + kc,     16);
        __pipeline_memcpy_async(d+3*TILE_E+8, s3 + kc + 8, 16);
        __pipeline_commit();
    }

    for (int i = 0; i < NCH; i++) {
        __pipeline_wait_prior(NSTG-2);
        __syncthreads();
        int nx = i + NSTG - 1;
        if (nx < NCH) {
            bf16* d = dbase + (nx % NSTG)*STG_E;
            int kc = nx*32;
            __pipeline_memcpy_async(d,            s0 + kc,     16);
            __pipeline_memcpy_async(d+8,          s0 + kc + 8, 16);
            __pipeline_memcpy_async(d+TILE_E,     s1 + kc,     16);
            __pipeline_memcpy_async(d+TILE_E+8,   s1 + kc + 8, 16);
            __pipeline_memcpy_async(d+2*TILE_E,   s2 + kc,     16);
            __pipeline_memcpy_async(d+2*TILE_E+8, s2 + kc + 8, 16);
            __pipeline_memcpy_async(d+3*TILE_E,   s3 + kc,     16);
            __pipeline_memcpy_async(d+3*TILE_E+8, s3 + kc + 8, 16);
        }
        __pipeline_commit();

        bf16* st  = sg + (i % NSTG)*STG_E;
        bf16* sAh = st;
        bf16* sAl = st + TILE_E;
        bf16* sBh = st + 2*TILE_E;
        bf16* sBl = st + 3*TILE_E;

        #pragma unroll
        for (int ks = 0; ks < 32; ks += 16) {
            wmma::fragment<wmma::matrix_a,16,16,16,bf16,
                           wmma::row_major> fah[2], fal[2];
            #pragma unroll
            for (int a=0;a<2;a++) {
                int mr = wm*32 + a*16;
                wmma::load_matrix_sync(fah[a], sAh + mr*ASTR + ks, ASTR);
                wmma::load_matrix_sync(fal[a], sAl + mr*ASTR + ks, ASTR);
            }
            #pragma unroll
            for (int j=0;j<4;j++) {
                int nr = wn*64 + j*16;
                wmma::fragment<wmma::matrix_b,16,16,16,bf16,
                               wmma::col_major> fbh, fbl;
                wmma::load_matrix_sync(fbh, sBh + nr*ASTR + ks, ASTR);
                wmma::load_matrix_sync(fbl, sBl + nr*ASTR + ks, ASTR);
                #pragma unroll
                for (int a=0;a<2;a++) {
                    wmma::mma_sync(acc[a][j], fah[a], fbh, acc[a][j]);
                    wmma::mma_sync(acc[a][j], fah[a], fbl, acc[a][j]);
                    wmma::mma_sync(acc[a][j], fal[a], fbh, acc[a][j]);
                }
            }
        }
    }

    __syncthreads();
    float* Sp = (float*)sg;
    #pragma unroll
    for (int a=0;a<2;a++)
      #pragma unroll
      for (int j=0;j<4;j++)
        wmma::store_matrix_sync(Sp + (wm*32+a*16)*132 + wn*64 + j*16,
                                acc[a][j], 132, wmma::mem_row_major);
    __syncthreads();
    {
        int r2 = tid >> 1, cs = (tid & 1) * 64;
        const float* sr = Sp + r2*132 + cs;
        size_t gb = (size_t)(m0 + r2) * Nd + n0 + cs;
        #pragma unroll
        for (int f = 0; f < 16; f++) {
            float4 v = *(const float4*)(sr + f*4);
            if (Cf) *(float4*)(Cf + gb + f*4) = v;
            if (Chi) {
                bf16 h0 = __float2bfloat16_rn(v.x);
                bf16 h1 = __float2bfloat16_rn(v.y);
                bf16 h2 = __float2bfloat16_rn(v.z);
                bf16 h3 = __float2bfloat16_rn(v.w);
                __nv_bfloat162 a0; a0.x = h0; a0.y = h1;
                __nv_bfloat162 a1; a1.x = h2; a1.y = h3;
                __nv_bfloat162 b0, b1;
                b0.x = __float2bfloat16_rn(v.x - __bfloat162float(h0));
                b0.y = __float2bfloat16_rn(v.y - __bfloat162float(h1));
                b1.x = __float2bfloat16_rn(v.z - __bfloat162float(h2));
                b1.y = __float2bfloat16_rn(v.w - __bfloat162float(h3));
                *(__nv_bfloat162*)(Chi + gb + f*4)     = a0;
                *(__nv_bfloat162*)(Chi + gb + f*4 + 2) = a1;
                *(__nv_bfloat162*)(Clo + gb + f*4)     = b0;
                *(__nv_bfloat162*)(Clo + gb + f*4 + 2) = b1;
            }
            if (Cb) {
                __nv_bfloat162 c0, c1;
                c0.x = __float2bfloat16_rn(v.x);
                c0.y = __float2bfloat16_rn(v.y);
                c1.x = __float2bfloat16_rn(v.z);
                c1.y = __float2bfloat16_rn(v.w);
                *(__nv_bfloat162*)(Cb + gb + f*4)     = c0;
                *(__nv_bfloat162*)(Cb + gb + f*4 + 2) = c1;
            }
        }
    }
}

// batched Q/K/V projections: z selects operands (from device globals)
__global__ __launch_bounds__(256) void gemm_qkv()
{
    extern __shared__ bf16 sg[];
    int z = blockIdx.z;
    int m0 = blockIdx.y * 128, n0 = blockIdx.x * 128;
    bf16* Chi = 0;
    bf16* Clo = 0;
    bf16* Cb = 0;
    if (z == 0) { Chi = g_qh; Clo = g_ql; }
    else if (z == 1) { Chi = g_kh; Clo = g_kl; }
    else { Cb = g_vb; }
    gemm_core(g_xh[z], g_xl[z], g_wh[z], g_wl[z],
              (float*)0, Chi, Clo, Cb, DM, DM, m0, n0, sg);
}

// output projection: ctx @ Wo^T -> g_O (fp32)
__global__ __launch_bounds__(256) void gemm_out()
{
    extern __shared__ bf16 sg[];
    int m0 = blockIdx.y * 128, n0 = blockIdx.x * 128;
    gemm_core(g_ch, g_cl, g_wh[3], g_wl[3],
              g_O, (bf16*)0, (bf16*)0, (bf16*)0, DM, DM, m0, n0, sg);
}

// ---------------- attention: wmma flash + fused band rescale ----------------
__global__ __launch_bounds__(256) void attn_wmma(
    const float* __restrict__ scp, const float* __restrict__ taup,
    const int* __restrict__ wsp, float* __restrict__ aout)
{
    extern __shared__ float sm[];
    float* Ss   = sm;                        // [128][72] fp32
    float* bias = Ss + 128*72;               // [1056] (reused as ilrow later)
    bf16* Qh = (bf16*)(bias + 1056);         // [128][72]
    bf16* Ql = Qh + 128*72;
    bf16* Kh = Ql + 128*72;                  // [64][72]
    bf16* Kl = Kh + 64*72;
    bf16* Vs = Kl + 64*72;
    bf16* Ps = Vs + 64*72;                   // [128][72]

    int tid = threadIdx.x;
    int wid = tid >> 5, lane = tid & 31;
    int h = blockIdx.y, b = blockIdx.z;
    int q0 = blockIdx.x * 128;
    int w2 = wsp[0] >> 1;
    float inv_s = 1.0f/scp[0], inv_tau = 1.0f/taup[0];

    for (int i = tid; i <= 2*w2 && i < 1056; i += 256)
        bias[i] = __expf(-fabsf((float)(i - w2)*inv_s)*inv_tau);

    {
        int qr = tid >> 1, seg = (tid & 1) * 32;
        size_t go = (size_t)(b*L_ + q0 + qr)*DM + h*DK + seg;
        const uint4* sh = (const uint4*)(g_qh + go);
        const uint4* sl = (const uint4*)(g_ql + go);
        uint4* dh = (uint4*)(Qh + qr*72 + seg);
        uint4* dl = (uint4*)(Ql + qr*72 + seg);
        #pragma unroll
        for (int f = 0; f < 4; f++) { dh[f] = sh[f]; dl[f] = sl[f]; }
    }
    __syncthreads();

    wmma::fragment<wmma::matrix_a,16,16,16,bf16,wmma::row_major> fqh[4];
    wmma::fragment<wmma::matrix_a,16,16,16,bf16,wmma::row_major> fql[4];
    #pragma unroll
    for (int s = 0; s < 4; s++) {
        wmma::load_matrix_sync(fqh[s], Qh + (wid*16)*72 + s*16, 72);
        wmma::load_matrix_sync(fql[s], Ql + (wid*16)*72 + s*16, 72);
    }

    wmma::fragment<wmma::accumulator,16,16,16,float> oacc[4];
    #pragma unroll
    for (int j = 0; j < 4; j++) wmma::fill_fragment(oacc[j], 0.0f);

    int lo = q0 - w2; if (lo < 0) lo = 0; lo &= ~63;
    int hi = q0 + 127 + w2; if (hi > L_-1) hi = L_-1;

    int rpar = lane >> 4;
    int c4 = lane & 15;
    float psum[8] = {0,0,0,0,0,0,0,0};
    float* aobase = 0;
    if (aout)
        aobase = aout + (size_t)((b*H_+h)*L_ + q0)*L_;

    for (int kvc = lo; kvc <= hi; kvc += 64) {
        __syncthreads();
        {
            int r = tid >> 2, seg = (tid & 3) * 16;
            size_t go = (size_t)(b*L_ + kvc + r)*DM + h*DK + seg;
            const uint4* skh = (const uint4*)(g_kh + go);
            const uint4* skl = (const uint4*)(g_kl + go);
            const uint4* sv  = (const uint4*)(g_vb + go);
            uint4* dkh = (uint4*)(Kh + r*72 + seg);
            uint4* dkl = (uint4*)(Kl + r*72 + seg);
            uint4* dv  = (uint4*)(Vs + r*72 + seg);
            dkh[0] = skh[0]; dkh[1] = skh[1];
            dkl[0] = skl[0]; dkl[1] = skl[1];
            dv[0]  = sv[0];  dv[1]  = sv[1];
        }
        __syncthreads();

        // S = Q @ K^T (3-term)
        #pragma unroll
        for (int j = 0; j < 4; j++) {
            wmma::fragment<wmma::accumulator,16,16,16,float> sacc;
            wmma::fill_fragment(sacc, 0.0f);
            #pragma unroll
            for (int s = 0; s < 4; s++) {
                wmma::fragment<wmma::matrix_b,16,16,16,bf16,
                               wmma::col_major> fbh, fbl;
                wmma::load_matrix_sync(fbh, Kh + (j*16)*72 + s*16, 72);
                wmma::load_matrix_sync(fbl, Kl + (j*16)*72 + s*16, 72);
                wmma::mma_sync(sacc, fqh[s], fbh, sacc);
                wmma::mma_sync(sacc, fqh[s], fbl, sacc);
                wmma::mma_sync(sacc, fql[s], fbh, sacc);
            }
            wmma::store_matrix_sync(Ss + (wid*16)*72 + j*16, sacc,
                                    72, wmma::mem_row_major);
        }
        __syncwarp();

        // epilogue: coalesced rows (16 lanes per row)
        #pragma unroll
        for (int rp = 0; rp < 8; rp++) {
            int r = wid*16 + rp*2 + rpar;
            float4 sv = *(const float4*)(Ss + r*72 + c4*4);
            int rel0 = kvc + c4*4 - (q0 + r);
            float p0 = 0.f, p1 = 0.f, p2 = 0.f, p3 = 0.f;
            if (rel0+0 >= -w2 && rel0+0 <= w2)
                p0 = __expf(sv.x*0.125f - bias[rel0+0+w2]);
            if (rel0+1 >= -w2 && rel0+1 <= w2)
                p1 = __expf(sv.y*0.125f - bias[rel0+1+w2]);
            if (rel0+2 >= -w2 && rel0+2 <= w2)
                p2 = __expf(sv.z*0.125f - bias[rel0+2+w2]);
            if (rel0+3 >= -w2 && rel0+3 <= w2)
                p3 = __expf(sv.w*0.125f - bias[rel0+3+w2]);
            psum[rp] += (p0 + p1) + (p2 + p3);
            if (aobase)
                *(float4*)(aobase + (size_t)r*L_ + kvc + c4*4) =
                    make_float4(p0, p1, p2, p3);
            __nv_bfloat162 k0, k1;
            k0.x = __float2bfloat16_rn(p0);
            k0.y = __float2bfloat16_rn(p1);
            k1.x = __float2bfloat16_rn(p2);
            k1.y = __float2bfloat16_rn(p3);
            bf16* prow = Ps + r*72 + c4*4;
            *(__nv_bfloat162*)prow       = k0;
            *(__nv_bfloat162*)(prow + 2) = k1;
        }
        __syncwarp();

        // O += P @ V
        {
            wmma::fragment<wmma::matrix_a,16,16,16,bf16,
                           wmma::row_major> fp[4];
            #pragma unroll
            for (int s = 0; s < 4; s++)
                wmma::load_matrix_sync(fp[s], Ps + (wid*16)*72 + s*16, 72);
            #pragma unroll
            for (int j = 0; j < 4; j++) {
                #pragma unroll
                for (int s = 0; s < 4; s++) {
                    wmma::fragment<wmma::matrix_b,16,16,16,bf16,
                                   wmma::row_major> fv;
                    wmma::load_matrix_sync(fv, Vs + (s*16)*72 + j*16, 72);
                    wmma::mma_sync(oacc[j], fp[s], fv, oacc[j]);
                }
            }
        }
    }

    // row sums -> 1/l
    #pragma unroll
    for (int rp = 0; rp < 8; rp++) {
        float l = psum[rp];
        l += __shfl_xor_sync(0xffffffffu, l, 1);
        l += __shfl_xor_sync(0xffffffffu, l, 2);
        l += __shfl_xor_sync(0xffffffffu, l, 4);
        l += __shfl_xor_sync(0xffffffffu, l, 8);
        psum[rp] = 1.0f / l;
    }

    // write normalized ctx as bf16 hi/lo
    __syncwarp();
    #pragma unroll
    for (int j = 0; j < 4; j++)
        wmma::store_matrix_sync(Ss + (wid*16)*72 + j*16, oacc[j],
                                72, wmma::mem_row_major);
    __syncwarp();
    #pragma unroll
    for (int rp = 0; rp < 8; rp++) {
        int r = wid*16 + rp*2 + rpar;
        float il = psum[rp];
        float4 v = *(const float4*)(Ss + r*72 + c4*4);
        v.x *= il; v.y *= il; v.z *= il; v.w *= il;
        bf16 h0 = __float2bfloat16_rn(v.x);
        bf16 h1 = __float2bfloat16_rn(v.y);
        bf16 h2 = __float2bfloat16_rn(v.z);
        bf16 h3 = __float2bfloat16_rn(v.w);
        __nv_bfloat162 a0; a0.x = h0; a0.y = h1;
        __nv_bfloat162 a1; a1.x = h2; a1.y = h3;
        __nv_bfloat162 b0, b1;
        b0.x = __float2bfloat16_rn(v.x - __bfloat162float(h0));
        b0.y = __float2bfloat16_rn(v.y - __bfloat162float(h1));
        b1.x = __float2bfloat16_rn(v.z - __bfloat162float(h2));
        b1.y = __float2bfloat16_rn(v.w - __bfloat162float(h3));
        size_t go = (size_t)(b*L_ + q0 + r)*DM + h*DK + c4*4;
        *(__nv_bfloat162*)(g_ch + go)     = a0;
        *(__nv_bfloat162*)(g_ch + go + 2) = a1;
        *(__nv_bfloat162*)(g_cl + go)     = b0;
        *(__nv_bfloat162*)(g_cl + go + 2) = b1;
    }

    // fused band rescale + zero fill (aout rows of this CTA, L2-hot)
    __syncthreads();               // all warps done with bias + band writes
    float* ilrow = bias;           // reuse smem
    if (c4 == 0) {
        #pragma unroll
        for (int rp = 0; rp < 8; rp++) {
            int r = wid*16 + rp*2 + rpar;
            ilrow[r] = psum[rp];
        }
    }
    __syncthreads();
    if (aobase) {
        int cend = (hi & ~63) + 64;
        #pragma unroll 4
        for (int it = 0; it < 256; it++) {
            int idx = it*256 + tid;
            int r = idx >> 9;
            int c = (idx & 511) * 4;
            float* addr = aobase + (size_t)r*L_ + c;
            float4 v;
            if (c >= lo && c < cend) {
                v = *(float4*)addr;
                float il = ilrow[r];
                v.x *= il; v.y *= il; v.z *= il; v.w *= il;
            } else {
                v = make_float4(0, 0, 0, 0);
            }
            *(float4*)addr = v;
        }
    }
}

// ---------------- residual + LayerNorm -------------------------------------
__global__ __launch_bounds__(256) void ln_kernel(
    const float* __restrict__ qin, const float* __restrict__ lnw,
    const float* __restrict__ lnb, float* __restrict__ out)
{
    __shared__ float sa[8], sb[8];
    int r = blockIdx.x;
    int tid = threadIdx.x;
    const float* o  = g_O + (size_t)r*DM;
    const float* qr = qin + (size_t)r*DM;

    float4 ov = *(const float4*)(o  + tid*4);
    float4 qv = *(const float4*)(qr + tid*4);
    float x0 = ov.x+qv.x, x1 = ov.y+qv.y, x2 = ov.z+qv.z, x3 = ov.w+qv.w;
    float sum = x0+x1+x2+x3;
    float sq  = x0*x0+x1*x1+x2*x2+x3*x3;

    #pragma unroll
    for (int off = 16; off > 0; off >>= 1) {
        sum += __shfl_down_sync(0xffffffffu, sum, off);
        sq  += __shfl_down_sync(0xffffffffu, sq,  off);
    }
    int w = tid >> 5, lane = tid & 31;
    if (lane == 0) { sa[w] = sum; sb[w] = sq; }
    __syncthreads();
    if (w == 0) {
        sum = (lane < 8) ? sa[lane] : 0.f;
        sq  = (lane < 8) ? sb[lane] : 0.f;
        #pragma unroll
        for (int off = 4; off > 0; off >>= 1) {
            sum += __shfl_down_sync(0xffffffffu, sum, off);
            sq  += __shfl_down_sync(0xffffffffu, sq,  off);
        }
        if (lane == 0) { sa[0] = sum; sb[0] = sq; }
    }
    __syncthreads();
    float mu  = sa[0] * (1.0f/DM);
    float var = sb[0] * (1.0f/DM) - mu*mu;
    float rstd = rsqrtf(var + 1e-6f);

    float4 wv = *(const float4*)(lnw + tid*4);
    float4 bv = *(const float4*)(lnb + tid*4);
    float4 ro;
    ro.x = (x0 - mu)*rstd*wv.x + bv.x;
    ro.y = (x1 - mu)*rstd*wv.y + bv.y;
    ro.z = (x2 - mu)*rstd*wv.z + bv.z;
    ro.w = (x3 - mu)*rstd*wv.w + bv.w;
    *(float4*)(out + (size_t)r*DM + tid*4) = ro;
}

// ---------------- launch -----------------------------------------------------
extern "C" void kernel_launch(void* const* d_in, const int* in_sizes, int n_in,
                              void* d_out, int out_size)
{
    const float* q    = (const float*)d_in[0];
    const float* k    = (const float*)d_in[1];
    const float* v    = (const float*)d_in[2];
    const float* Wq   = (const float*)d_in[4];
    const float* Wk   = (const float*)d_in[5];
    const float* Wv   = (const float*)d_in[6];
    const float* Wo   = (const float*)d_in[7];
    const float* scp  = (const float*)d_in[8];
    const float* taup = (const float*)d_in[9];
    const float* lnw  = (const float*)d_in[10];
    const float* lnb  = (const float*)d_in[11];
    const int*   wsp  = (const int*)  d_in[12];

    bf16 *xh, *xl, *wh, *wl;
    cudaGetSymbolAddress((void**)&xh, g_xh);
    cudaGetSymbolAddress((void**)&xl, g_xl);
    cudaGetSymbolAddress((void**)&wh, g_wh);
    cudaGetSymbolAddress((void**)&wl, g_wl);

    size_t osz = (size_t)out_size;
    float* xout = nullptr;
    float* aout = nullptr;
    if (osz >= X_ELEMS + ATT_ELEMS) {
        xout = (float*)d_out;
        aout = (float*)d_out + X_ELEMS;
    } else if (osz >= X_ELEMS) {
        xout = (float*)d_out;
    } else if (osz >= ATT_ELEMS) {
        aout = (float*)d_out;
    }

    const int ATTN_SMEM = (128*72 + 1056)*4 + (128*72*3 + 64*72*3)*2;
    cudaFuncSetAttribute(attn_wmma,
        cudaFuncAttributeMaxDynamicSharedMemorySize, ATTN_SMEM);
    cudaFuncSetAttribute(gemm_qkv,
        cudaFuncAttributeMaxDynamicSharedMemorySize, GEMM_SMEM);
    cudaFuncSetAttribute(gemm_out,
        cudaFuncAttributeMaxDynamicSharedMemorySize, GEMM_SMEM);

    const int XN4 = (int)(X_ELEMS/4), WN4 = DM*DM/4;
    const size_t WS = (size_t)DM*DM;
    cvt_hilo<<<XN4/256, 256>>>(q, xh, xl, XN4);
    cvt_hilo<<<XN4/256, 256>>>(k, xh + X_ELEMS, xl + X_ELEMS, XN4);
    cvt_hilo<<<XN4/256, 256>>>(v, xh + 2*X_ELEMS, xl + 2*X_ELEMS, XN4);
    cvt_hilo<<<WN4/256, 256>>>(Wq, wh, wl, WN4);
    cvt_hilo<<<WN4/256, 256>>>(Wk, wh + WS, wl + WS, WN4);
    cvt_hilo<<<WN4/256, 256>>>(Wv, wh + 2*WS, wl + 2*WS, WN4);
    cvt_hilo<<<WN4/256, 256>>>(Wo, wh + 3*WS, wl + 3*WS, WN4);

    dim3 gQKV(DM/128, M_/128, 3);
    gemm_qkv<<<gQKV, 256, GEMM_SMEM>>>();

    dim3 gAttn(L_/128, H_, B_);
    attn_wmma<<<gAttn, 256, ATTN_SMEM>>>(scp, taup, wsp, aout);

    dim3 gGemm(DM/128, M_/128);
    gemm_out<<<gGemm, 256, GEMM_SMEM>>>();

    if (xout)
        ln_kernel<<<M_, 256>>>(q, lnw, lnb, xout);
}

// round 13
// speedup vs baseline: 1.3170x; 1.3170x over previous
#include <cuda_runtime.h>
#include <cuda_bf16.h>
#include <cuda_pipeline.h>
#include <mma.h>
#include <math.h>

using namespace nvcuda;
typedef unsigned long long ull;
typedef __nv_bfloat16 bf16;

#define B_  2
#define L_  2048
#define DM  1024
#define H_  16
#define DK  64
#define M_  (B_*L_)

#define X_ELEMS   ((size_t)M_*DM)
#define ATT_ELEMS ((size_t)B_*H_*L_*L_)

__device__ float g_O[M_*DM];
__device__ float g_il[B_*H_*L_];
__device__ bf16 g_xh[3][M_*DM];
__device__ bf16 g_xl[3][M_*DM];
__device__ bf16 g_wh[4][DM*DM];
__device__ bf16 g_wl[4][DM*DM];
__device__ bf16 g_ch[M_*DM];
__device__ bf16 g_cl[M_*DM];
__device__ bf16 g_qh[M_*DM];
__device__ bf16 g_ql[M_*DM];
__device__ bf16 g_kh[M_*DM];
__device__ bf16 g_kl[M_*DM];
__device__ bf16 g_vb[M_*DM];

// ---------------- fused fp32 -> bf16 hi/lo split (all 7 tensors) ------------
#define XN4 ((int)(X_ELEMS/4))
#define WN4 (DM*DM/4)

__device__ __forceinline__ void hilo4(float4 v, bf16* hi, bf16* lo, size_t i4)
{
    bf16 h0 = __float2bfloat16_rn(v.x);
    bf16 h1 = __float2bfloat16_rn(v.y);
    bf16 h2 = __float2bfloat16_rn(v.z);
    bf16 h3 = __float2bfloat16_rn(v.w);
    __nv_bfloat162 a0; a0.x = h0; a0.y = h1;
    __nv_bfloat162 a1; a1.x = h2; a1.y = h3;
    __nv_bfloat162 b0, b1;
    b0.x = __float2bfloat16_rn(v.x - __bfloat162float(h0));
    b0.y = __float2bfloat16_rn(v.y - __bfloat162float(h1));
    b1.x = __float2bfloat16_rn(v.z - __bfloat162float(h2));
    b1.y = __float2bfloat16_rn(v.w - __bfloat162float(h3));
    ((__nv_bfloat162*)hi)[i4*2+0] = a0;
    ((__nv_bfloat162*)hi)[i4*2+1] = a1;
    ((__nv_bfloat162*)lo)[i4*2+0] = b0;
    ((__nv_bfloat162*)lo)[i4*2+1] = b1;
}

__global__ __launch_bounds__(256) void cvt_all(
    const float* __restrict__ q, const float* __restrict__ k,
    const float* __restrict__ v, const float* __restrict__ Wq,
    const float* __restrict__ Wk, const float* __restrict__ Wv,
    const float* __restrict__ Wo)
{
    int i = blockIdx.x * 256 + threadIdx.x;
    if (i < 3*XN4) {
        int z = i / XN4;
        int r = i - z*XN4;
        const float* src = (z == 0) ? q : (z == 1) ? k : v;
        float4 val = ((const float4*)src)[r];
        hilo4(val, g_xh[z], g_xl[z], (size_t)r);
    } else {
        int j = i - 3*XN4;
        int w = j / WN4;
        int r = j - w*WN4;
        const float* src = (w == 0) ? Wq : (w == 1) ? Wk
                         : (w == 2) ? Wv : Wo;
        float4 val = ((const float4*)src)[r];
        hilo4(val, g_wh[w], g_wl[w], (size_t)r);
    }
}

// ---------------- pipelined wmma GEMM core: C = A @ B^T ---------------------
// 3-term bf16 hi/lo, fp32 accum, BK=16, cp.async 3-stage ring.
#define ASTR 24
#define NSTG 3
#define TILE_E (128*ASTR)
#define STG_E  (4*TILE_E)
#define GEMM_SMEM (NSTG*STG_E*2)

__device__ __forceinline__ void gemm_core(
    const bf16* __restrict__ Ah, const bf16* __restrict__ Al,
    const bf16* __restrict__ Bh, const bf16* __restrict__ Bl,
    float* Cf, bf16* Chi, bf16* Clo, bf16* Cb,
    int Nd, int Kd, int m0, int n0, bf16* sg)
{
    int tid = threadIdx.x;
    int wid = tid >> 5;
    int wm = wid >> 1, wn = wid & 1;

    wmma::fragment<wmma::accumulator,16,16,16,float> acc[2][4];
    #pragma unroll
    for (int i=0;i<2;i++)
      #pragma unroll
      for (int j=0;j<4;j++) wmma::fill_fragment(acc[i][j], 0.0f);

    int row = tid >> 1, seg = (tid & 1) * 8;
    const bf16* s0 = Ah + (size_t)(m0+row)*Kd + seg;
    const bf16* s1 = Al + (size_t)(m0+row)*Kd + seg;
    const bf16* s2 = Bh + (size_t)(n0+row)*Kd + seg;
    const bf16* s3 = Bl + (size_t)(n0+row)*Kd + seg;
    bf16* dbase = sg + row*ASTR + seg;

    int NCH = Kd >> 4;
    #pragma unroll
    for (int s = 0; s < NSTG-1; s++) {
        bf16* d = dbase + s*STG_E;
        int kc = s*16;
        __pipeline_memcpy_async(d,          s0 + kc, 16);
        __pipeline_memcpy_async(d+TILE_E,   s1 + kc, 16);
        __pipeline_memcpy_async(d+2*TILE_E, s2 + kc, 16);
        __pipeline_memcpy_async(d+3*TILE_E, s3 + kc, 16);
        __pipeline_commit();
    }

    for (int i = 0; i < NCH; i++) {
        __pipeline_wait_prior(NSTG-2);
        __syncthreads();
        int nx = i + NSTG - 1;
        if (nx < NCH) {
            bf16* d = dbase + (nx % NSTG)*STG_E;
            int kc = nx*16;
            __pipeline_memcpy_async(d,          s0 + kc, 16);
            __pipeline_memcpy_async(d+TILE_E,   s1 + kc, 16);
            __pipeline_memcpy_async(d+2*TILE_E, s2 + kc, 16);
            __pipeline_memcpy_async(d+3*TILE_E, s3 + kc, 16);
        }
        __pipeline_commit();

        bf16* st  = sg + (i % NSTG)*STG_E;
        bf16* sAh = st;
        bf16* sAl = st + TILE_E;
        bf16* sBh = st + 2*TILE_E;
        bf16* sBl = st + 3*TILE_E;

        wmma::fragment<wmma::matrix_a,16,16,16,bf16,wmma::row_major> fah[2];
        wmma::fragment<wmma::matrix_a,16,16,16,bf16,wmma::row_major> fal[2];
        #pragma unroll
        for (int a=0;a<2;a++) {
            int mr = wm*32 + a*16;
            wmma::load_matrix_sync(fah[a], sAh + mr*ASTR, ASTR);
            wmma::load_matrix_sync(fal[a], sAl + mr*ASTR, ASTR);
        }
        #pragma unroll
        for (int j=0;j<4;j++) {
            int nr = wn*64 + j*16;
            wmma::fragment<wmma::matrix_b,16,16,16,bf16,wmma::col_major> fbh;
            wmma::fragment<wmma::matrix_b,16,16,16,bf16,wmma::col_major> fbl;
            wmma::load_matrix_sync(fbh, sBh + nr*ASTR, ASTR);
            wmma::load_matrix_sync(fbl, sBl + nr*ASTR, ASTR);
            #pragma unroll
            for (int a=0;a<2;a++) {
                wmma::mma_sync(acc[a][j], fah[a], fbh, acc[a][j]);
                wmma::mma_sync(acc[a][j], fah[a], fbl, acc[a][j]);
                wmma::mma_sync(acc[a][j], fal[a], fbh, acc[a][j]);
            }
        }
    }

    __syncthreads();
    float* Sp = (float*)sg;
    #pragma unroll
    for (int a=0;a<2;a++)
      #pragma unroll
      for (int j=0;j<4;j++)
        wmma::store_matrix_sync(Sp + (wm*32+a*16)*132 + wn*64 + j*16,
                                acc[a][j], 132, wmma::mem_row_major);
    __syncthreads();
    {
        int r2 = tid >> 1, cs = (tid & 1) * 64;
        const float* sr = Sp + r2*132 + cs;
        size_t gb = (size_t)(m0 + r2) * Nd + n0 + cs;
        #pragma unroll
        for (int f = 0; f < 16; f++) {
            float4 v = *(const float4*)(sr + f*4);
            if (Cf) *(float4*)(Cf + gb + f*4) = v;
            if (Chi) {
                bf16 h0 = __float2bfloat16_rn(v.x);
                bf16 h1 = __float2bfloat16_rn(v.y);
                bf16 h2 = __float2bfloat16_rn(v.z);
                bf16 h3 = __float2bfloat16_rn(v.w);
                __nv_bfloat162 a0; a0.x = h0; a0.y = h1;
                __nv_bfloat162 a1; a1.x = h2; a1.y = h3;
                __nv_bfloat162 b0, b1;
                b0.x = __float2bfloat16_rn(v.x - __bfloat162float(h0));
                b0.y = __float2bfloat16_rn(v.y - __bfloat162float(h1));
                b1.x = __float2bfloat16_rn(v.z - __bfloat162float(h2));
                b1.y = __float2bfloat16_rn(v.w - __bfloat162float(h3));
                *(__nv_bfloat162*)(Chi + gb + f*4)     = a0;
                *(__nv_bfloat162*)(Chi + gb + f*4 + 2) = a1;
                *(__nv_bfloat162*)(Clo + gb + f*4)     = b0;
                *(__nv_bfloat162*)(Clo + gb + f*4 + 2) = b1;
            }
            if (Cb) {
                __nv_bfloat162 c0, c1;
                c0.x = __float2bfloat16_rn(v.x);
                c0.y = __float2bfloat16_rn(v.y);
                c1.x = __float2bfloat16_rn(v.z);
                c1.y = __float2bfloat16_rn(v.w);
                *(__nv_bfloat162*)(Cb + gb + f*4)     = c0;
                *(__nv_bfloat162*)(Cb + gb + f*4 + 2) = c1;
            }
        }
    }
}

// batched Q/K/V projections: z selects operands (from device globals)
__global__ __launch_bounds__(256) void gemm_qkv()
{
    extern __shared__ bf16 sg[];
    int z = blockIdx.z;
    int m0 = blockIdx.y * 128, n0 = blockIdx.x * 128;
    bf16* Chi = 0;
    bf16* Clo = 0;
    bf16* Cb = 0;
    if (z == 0) { Chi = g_qh; Clo = g_ql; }
    else if (z == 1) { Chi = g_kh; Clo = g_kl; }
    else { Cb = g_vb; }
    gemm_core(g_xh[z], g_xl[z], g_wh[z], g_wl[z],
              (float*)0, Chi, Clo, Cb, DM, DM, m0, n0, sg);
}

// output projection: ctx @ Wo^T -> g_O (fp32)
__global__ __launch_bounds__(256) void gemm_out()
{
    extern __shared__ bf16 sg[];
    int m0 = blockIdx.y * 128, n0 = blockIdx.x * 128;
    gemm_core(g_ch, g_cl, g_wh[3], g_wl[3],
              g_O, (bf16*)0, (bf16*)0, (bf16*)0, DM, DM, m0, n0, sg);
}

// ---------------- attention: wmma flash, fixed max (m=0) --------------------
__global__ __launch_bounds__(256) void attn_wmma(
    const float* __restrict__ scp, const float* __restrict__ taup,
    const int* __restrict__ wsp, float* __restrict__ aout)
{
    extern __shared__ float sm[];
    float* Ss   = sm;                        // [128][72] fp32
    float* bias = Ss + 128*72;               // [1056]
    bf16* Qh = (bf16*)(bias + 1056);         // [128][72]
    bf16* Ql = Qh + 128*72;
    bf16* Kh = Ql + 128*72;                  // [64][72]
    bf16* Kl = Kh + 64*72;
    bf16* Vs = Kl + 64*72;
    bf16* Ps = Vs + 64*72;                   // [128][72]

    int tid = threadIdx.x;
    int wid = tid >> 5, lane = tid & 31;
    int h = blockIdx.y, b = blockIdx.z;
    int q0 = blockIdx.x * 128;
    int w2 = wsp[0] >> 1;
    float inv_s = 1.0f/scp[0], inv_tau = 1.0f/taup[0];

    for (int i = tid; i <= 2*w2 && i < 1056; i += 256)
        bias[i] = __expf(-fabsf((float)(i - w2)*inv_s)*inv_tau);

    {
        int qr = tid >> 1, seg = (tid & 1) * 32;
        size_t go = (size_t)(b*L_ + q0 + qr)*DM + h*DK + seg;
        const uint4* sh = (const uint4*)(g_qh + go);
        const uint4* sl = (const uint4*)(g_ql + go);
        uint4* dh = (uint4*)(Qh + qr*72 + seg);
        uint4* dl = (uint4*)(Ql + qr*72 + seg);
        #pragma unroll
        for (int f = 0; f < 4; f++) { dh[f] = sh[f]; dl[f] = sl[f]; }
    }
    __syncthreads();

    wmma::fragment<wmma::matrix_a,16,16,16,bf16,wmma::row_major> fqh[4];
    wmma::fragment<wmma::matrix_a,16,16,16,bf16,wmma::row_major> fql[4];
    #pragma unroll
    for (int s = 0; s < 4; s++) {
        wmma::load_matrix_sync(fqh[s], Qh + (wid*16)*72 + s*16, 72);
        wmma::load_matrix_sync(fql[s], Ql + (wid*16)*72 + s*16, 72);
    }

    wmma::fragment<wmma::accumulator,16,16,16,float> oacc[4];
    #pragma unroll
    for (int j = 0; j < 4; j++) wmma::fill_fragment(oacc[j], 0.0f);

    int lo = q0 - w2; if (lo < 0) lo = 0; lo &= ~63;
    int hi = q0 + 127 + w2; if (hi > L_-1) hi = L_-1;

    int rpar = lane >> 4;
    int c4 = lane & 15;
    float psum[8] = {0,0,0,0,0,0,0,0};
    float* aobase = 0;
    if (aout)
        aobase = aout + (size_t)((b*H_+h)*L_ + q0)*L_;

    for (int kvc = lo; kvc <= hi; kvc += 64) {
        __syncthreads();
        {
            int r = tid >> 2, seg = (tid & 3) * 16;
            size_t go = (size_t)(b*L_ + kvc + r)*DM + h*DK + seg;
            const uint4* skh = (const uint4*)(g_kh + go);
            const uint4* skl = (const uint4*)(g_kl + go);
            const uint4* sv  = (const uint4*)(g_vb + go);
            uint4* dkh = (uint4*)(Kh + r*72 + seg);
            uint4* dkl = (uint4*)(Kl + r*72 + seg);
            uint4* dv  = (uint4*)(Vs + r*72 + seg);
            dkh[0] = skh[0]; dkh[1] = skh[1];
            dkl[0] = skl[0]; dkl[1] = skl[1];
            dv[0]  = sv[0];  dv[1]  = sv[1];
        }
        __syncthreads();

        // S = Q @ K^T (3-term)
        #pragma unroll
        for (int j = 0; j < 4; j++) {
            wmma::fragment<wmma::accumulator,16,16,16,float> sacc;
            wmma::fill_fragment(sacc, 0.0f);
            #pragma unroll
            for (int s = 0; s < 4; s++) {
                wmma::fragment<wmma::matrix_b,16,16,16,bf16,
                               wmma::col_major> fbh, fbl;
                wmma::load_matrix_sync(fbh, Kh + (j*16)*72 + s*16, 72);
                wmma::load_matrix_sync(fbl, Kl + (j*16)*72 + s*16, 72);
                wmma::mma_sync(sacc, fqh[s], fbh, sacc);
                wmma::mma_sync(sacc, fqh[s], fbl, sacc);
                wmma::mma_sync(sacc, fql[s], fbh, sacc);
            }
            wmma::store_matrix_sync(Ss + (wid*16)*72 + j*16, sacc,
                                    72, wmma::mem_row_major);
        }
        __syncwarp();

        // epilogue: coalesced rows (16 lanes per row)
        #pragma unroll
        for (int rp = 0; rp < 8; rp++) {
            int r = wid*16 + rp*2 + rpar;
            float4 sv = *(const float4*)(Ss + r*72 + c4*4);
            int rel0 = kvc + c4*4 - (q0 + r);
            float p0 = 0.f, p1 = 0.f, p2 = 0.f, p3 = 0.f;
            if (rel0+0 >= -w2 && rel0+0 <= w2)
                p0 = __expf(sv.x*0.125f - bias[rel0+0+w2]);
            if (rel0+1 >= -w2 && rel0+1 <= w2)
                p1 = __expf(sv.y*0.125f - bias[rel0+1+w2]);
            if (rel0+2 >= -w2 && rel0+2 <= w2)
                p2 = __expf(sv.z*0.125f - bias[rel0+2+w2]);
            if (rel0+3 >= -w2 && rel0+3 <= w2)
                p3 = __expf(sv.w*0.125f - bias[rel0+3+w2]);
            psum[rp] += (p0 + p1) + (p2 + p3);
            if (aobase)
                *(float4*)(aobase + (size_t)r*L_ + kvc + c4*4) =
                    make_float4(p0, p1, p2, p3);
            __nv_bfloat162 k0, k1;
            k0.x = __float2bfloat16_rn(p0);
            k0.y = __float2bfloat16_rn(p1);
            k1.x = __float2bfloat16_rn(p2);
            k1.y = __float2bfloat16_rn(p3);
            bf16* prow = Ps + r*72 + c4*4;
            *(__nv_bfloat162*)prow       = k0;
            *(__nv_bfloat162*)(prow + 2) = k1;
        }
        __syncwarp();

        // O += P @ V
        {
            wmma::fragment<wmma::matrix_a,16,16,16,bf16,
                           wmma::row_major> fp[4];
            #pragma unroll
            for (int s = 0; s < 4; s++)
                wmma::load_matrix_sync(fp[s], Ps + (wid*16)*72 + s*16, 72);
            #pragma unroll
            for (int j = 0; j < 4; j++) {
                #pragma unroll
                for (int s = 0; s < 4; s++) {
                    wmma::fragment<wmma::matrix_b,16,16,16,bf16,
                                   wmma::row_major> fv;
                    wmma::load_matrix_sync(fv, Vs + (s*16)*72 + j*16, 72);
                    wmma::mma_sync(oacc[j], fp[s], fv, oacc[j]);
                }
            }
        }
    }

    // row sums -> 1/l
    #pragma unroll
    for (int rp = 0; rp < 8; rp++) {
        float l = psum[rp];
        l += __shfl_xor_sync(0xffffffffu, l, 1);
        l += __shfl_xor_sync(0xffffffffu, l, 2);
        l += __shfl_xor_sync(0xffffffffu, l, 4);
        l += __shfl_xor_sync(0xffffffffu, l, 8);
        psum[rp] = 1.0f / l;
    }
    if (c4 == 0) {
        #pragma unroll
        for (int rp = 0; rp < 8; rp++) {
            int r = wid*16 + rp*2 + rpar;
            g_il[(b*H_+h)*L_ + q0 + r] = psum[rp];
        }
    }

    __syncwarp();
    #pragma unroll
    for (int j = 0; j < 4; j++)
        wmma::store_matrix_sync(Ss + (wid*16)*72 + j*16, oacc[j],
                                72, wmma::mem_row_major);
    __syncwarp();
    #pragma unroll
    for (int rp = 0; rp < 8; rp++) {
        int r = wid*16 + rp*2 + rpar;
        float il = psum[rp];
        float4 v = *(const float4*)(Ss + r*72 + c4*4);
        v.x *= il; v.y *= il; v.z *= il; v.w *= il;
        bf16 h0 = __float2bfloat16_rn(v.x);
        bf16 h1 = __float2bfloat16_rn(v.y);
        bf16 h2 = __float2bfloat16_rn(v.z);
        bf16 h3 = __float2bfloat16_rn(v.w);
        __nv_bfloat162 a0; a0.x = h0; a0.y = h1;
        __nv_bfloat162 a1; a1.x = h2; a1.y = h3;
        __nv_bfloat162 b0, b1;
        b0.x = __float2bfloat16_rn(v.x - __bfloat162float(h0));
        b0.y = __float2bfloat16_rn(v.y - __bfloat162float(h1));
        b1.x = __float2bfloat16_rn(v.z - __bfloat162float(h2));
        b1.y = __float2bfloat16_rn(v.w - __bfloat162float(h3));
        size_t go = (size_t)(b*L_ + q0 + r)*DM + h*DK + c4*4;
        *(__nv_bfloat162*)(g_ch + go)     = a0;
        *(__nv_bfloat162*)(g_ch + go + 2) = a1;
        *(__nv_bfloat162*)(g_cl + go)     = b0;
        *(__nv_bfloat162*)(g_cl + go + 2) = b1;
    }
}

// ---------------- attention finalize: scale band by 1/l, zero outside -------
__global__ __launch_bounds__(256) void attn_scale(
    float* __restrict__ attn, const int* __restrict__ ws_p)
{
    int row = blockIdx.x;
    int qi = row & (L_-1);
    float il = g_il[row];
    int w2 = ws_p[0] >> 1;
    int lo = qi - w2; if (lo < 0) lo = 0;
    int hi = qi + w2; if (hi > L_-1) hi = L_-1;
    float4* p = (float4*)(attn + (size_t)row*L_);
    #pragma unroll
    for (int it = 0; it < (L_/4)/256; it++) {
        int c4 = it*256 + threadIdx.x;
        int c0 = c4*4;
        float4 v;
        if (c0 >= lo && c0+3 <= hi) {
            v = p[c4];
            v.x *= il; v.y *= il; v.z *= il; v.w *= il;
        } else if (c0+3 < lo || c0 > hi) {
            v = make_float4(0,0,0,0);
        } else {
            float4 t = p[c4];
            v.x = (c0+0>=lo && c0+0<=hi) ? t.x*il : 0.f;
            v.y = (c0+1>=lo && c0+1<=hi) ? t.y*il : 0.f;
            v.z = (c0+2>=lo && c0+2<=hi) ? t.z*il : 0.f;
            v.w = (c0+3>=lo && c0+3<=hi) ? t.w*il : 0.f;
        }
        p[c4] = v;
    }
}

// ---------------- residual + LayerNorm -------------------------------------
__global__ __launch_bounds__(256) void ln_kernel(
    const float* __restrict__ qin, const float* __restrict__ lnw,
    const float* __restrict__ lnb, float* __restrict__ out)
{
    __shared__ float sa[8], sb[8];
    int r = blockIdx.x;
    int tid = threadIdx.x;
    const float* o  = g_O + (size_t)r*DM;
    const float* qr = qin + (size_t)r*DM;

    float4 ov = *(const float4*)(o  + tid*4);
    float4 qv = *(const float4*)(qr + tid*4);
    float x0 = ov.x+qv.x, x1 = ov.y+qv.y, x2 = ov.z+qv.z, x3 = ov.w+qv.w;
    float sum = x0+x1+x2+x3;
    float sq  = x0*x0+x1*x1+x2*x2+x3*x3;

    #pragma unroll
    for (int off = 16; off > 0; off >>= 1) {
        sum += __shfl_down_sync(0xffffffffu, sum, off);
        sq  += __shfl_down_sync(0xffffffffu, sq,  off);
    }
    int w = tid >> 5, lane = tid & 31;
    if (lane == 0) { sa[w] = sum; sb[w] = sq; }
    __syncthreads();
    if (w == 0) {
        sum = (lane < 8) ? sa[lane] : 0.f;
        sq  = (lane < 8) ? sb[lane] : 0.f;
        #pragma unroll
        for (int off = 4; off > 0; off >>= 1) {
            sum += __shfl_down_sync(0xffffffffu, sum, off);
            sq  += __shfl_down_sync(0xffffffffu, sq,  off);
        }
        if (lane == 0) { sa[0] = sum; sb[0] = sq; }
    }
    __syncthreads();
    float mu  = sa[0] * (1.0f/DM);
    float var = sb[0] * (1.0f/DM) - mu*mu;
    float rstd = rsqrtf(var + 1e-6f);

    float4 wv = *(const float4*)(lnw + tid*4);
    float4 bv = *(const float4*)(lnb + tid*4);
    float4 ro;
    ro.x = (x0 - mu)*rstd*wv.x + bv.x;
    ro.y = (x1 - mu)*rstd*wv.y + bv.y;
    ro.z = (x2 - mu)*rstd*wv.z + bv.z;
    ro.w = (x3 - mu)*rstd*wv.w + bv.w;
    *(float4*)(out + (size_t)r*DM + tid*4) = ro;
}

// ---------------- launch -----------------------------------------------------
extern "C" void kernel_launch(void* const* d_in, const int* in_sizes, int n_in,
                              void* d_out, int out_size)
{
    const float* q    = (const float*)d_in[0];
    const float* k    = (const float*)d_in[1];
    const float* v    = (const float*)d_in[2];
    const float* Wq   = (const float*)d_in[4];
    const float* Wk   = (const float*)d_in[5];
    const float* Wv   = (const float*)d_in[6];
    const float* Wo   = (const float*)d_in[7];
    const float* scp  = (const float*)d_in[8];
    const float* taup = (const float*)d_in[9];
    const float* lnw  = (const float*)d_in[10];
    const float* lnb  = (const float*)d_in[11];
    const int*   wsp  = (const int*)  d_in[12];

    size_t osz = (size_t)out_size;
    float* xout = nullptr;
    float* aout = nullptr;
    if (osz >= X_ELEMS + ATT_ELEMS) {
        xout = (float*)d_out;
        aout = (float*)d_out + X_ELEMS;
    } else if (osz >= X_ELEMS) {
        xout = (float*)d_out;
    } else if (osz >= ATT_ELEMS) {
        aout = (float*)d_out;
    }

    const int ATTN_SMEM = (128*72 + 1056)*4 + (128*72*3 + 64*72*3)*2;
    cudaFuncSetAttribute(attn_wmma,
        cudaFuncAttributeMaxDynamicSharedMemorySize, ATTN_SMEM);
    cudaFuncSetAttribute(gemm_qkv,
        cudaFuncAttributeMaxDynamicSharedMemorySize, GEMM_SMEM);
    cudaFuncSetAttribute(gemm_out,
        cudaFuncAttributeMaxDynamicSharedMemorySize, GEMM_SMEM);

    int CVT_TOT = 3*XN4 + 4*WN4;
    cvt_all<<<CVT_TOT/256, 256>>>(q, k, v, Wq, Wk, Wv, Wo);

    dim3 gQKV(DM/128, M_/128, 3);
    gemm_qkv<<<gQKV, 256, GEMM_SMEM>>>();

    dim3 gAttn(L_/128, H_, B_);
    attn_wmma<<<gAttn, 256, ATTN_SMEM>>>(scp, taup, wsp, aout);

    dim3 gGemm(DM/128, M_/128);
    gemm_out<<<gGemm, 256, GEMM_SMEM>>>();

    if (aout)
        attn_scale<<<B_*H_*L_, 256>>>(aout, wsp);
    if (xout)
        ln_kernel<<<M_, 256>>>(q, lnw, lnb, xout);
}